// round 1
// baseline (speedup 1.0000x reference)
#include <cuda_runtime.h>
#include <cuda_bf16.h>

typedef unsigned int uint;

// ---------------- scratch (device globals; no allocs allowed) ----------------
__device__ float g_q[2048L * 64 * 256];    // 128 MB : q projection
__device__ float g_kv[4096L * 64 * 512];   // 512 MB : kv projection
__device__ float g_att[4096L * 64 * 256];  // 256 MB : attention output (pre-proj)

#define DEV_INLINE __device__ __forceinline__

DEV_INLINE void mma16816(float* d, const uint* a, const uint* b) {
    asm volatile(
        "mma.sync.aligned.m16n8k16.row.col.f32.bf16.bf16.f32 "
        "{%0,%1,%2,%3}, {%4,%5,%6,%7}, {%8,%9}, {%0,%1,%2,%3};\n"
        : "+f"(d[0]), "+f"(d[1]), "+f"(d[2]), "+f"(d[3])
        : "r"(a[0]), "r"(a[1]), "r"(a[2]), "r"(a[3]), "r"(b[0]), "r"(b[1]));
}

DEV_INLINE uint lds_u32(const __nv_bfloat16* p) {
    return *reinterpret_cast<const uint*>(p);
}

// split fp32 pair into bf16 (hi) + bf16 (residual lo), store both to smem
DEV_INLINE void split_store(float x, float y, __nv_bfloat16* hi_p, __nv_bfloat16* lo_p) {
    __nv_bfloat162 h = __floats2bfloat162_rn(x, y);
    __nv_bfloat162 l = __floats2bfloat162_rn(x - __bfloat162float(h.x),
                                             y - __bfloat162float(h.y));
    *reinterpret_cast<__nv_bfloat162*>(hi_p) = h;
    *reinterpret_cast<__nv_bfloat162*>(lo_p) = l;
}

// split fp32 pair into packed bf16x2 hi + lo registers (for P frags)
DEV_INLINE void packsplit(float x, float y, uint& hi, uint& lo) {
    __nv_bfloat162 h = __floats2bfloat162_rn(x, y);
    __nv_bfloat162 l = __floats2bfloat162_rn(x - __bfloat162float(h.x),
                                             y - __bfloat162float(h.y));
    hi = *reinterpret_cast<uint*>(&h);
    lo = *reinterpret_cast<uint*>(&l);
}

// =============================================================================
// GEMM: C[M,N] = A[M,K] @ B[N,K]^T + bias[N]   (K = 256, bf16x3 compensated)
// Tiles: BM=128, BN=128, BK=32. 256 threads (8 warps, 4m x 2n, warp = 32x64).
// grid: (N/128, M/128) — n-fastest so A-tile rereads hit L2.
// =============================================================================
__global__ __launch_bounds__(256, 1) void gemm_bias_kernel(
    const float* __restrict__ A, const float* __restrict__ B,
    const float* __restrict__ bias, float* __restrict__ C, int N)
{
    constexpr int K = 256;
    constexpr int LDT = 40;        // smem row stride in bf16 (32 + 8 pad, conflict-free)
    constexpr int STG = 20480;     // bf16 elements per stage (Ahi|Alo|Bhi|Blo, 5120 each)
    extern __shared__ __nv_bfloat16 sm[];

    const int tid = threadIdx.x;
    const int m0 = blockIdx.y * 128;
    const int n0 = blockIdx.x * 128;

    auto load_stage = [&](int k0, __nv_bfloat16* st) {
        #pragma unroll
        for (int u = 0; u < 4; u++) {                    // A: 128x32 = 1024 float4
            int f = tid + u * 256;
            int r = f >> 3;
            int c = (f & 7) << 2;
            float4 v = *reinterpret_cast<const float4*>(A + (size_t)(m0 + r) * K + k0 + c);
            __nv_bfloat16* hp = st + r * LDT + c;
            __nv_bfloat16* lp = st + 5120 + r * LDT + c;
            split_store(v.x, v.y, hp, lp);
            split_store(v.z, v.w, hp + 2, lp + 2);
        }
        #pragma unroll
        for (int u = 0; u < 4; u++) {                    // B: 128x32
            int f = tid + u * 256;
            int r = f >> 3;
            int c = (f & 7) << 2;
            float4 v = *reinterpret_cast<const float4*>(B + (size_t)(n0 + r) * K + k0 + c);
            __nv_bfloat16* hp = st + 10240 + r * LDT + c;
            __nv_bfloat16* lp = st + 15360 + r * LDT + c;
            split_store(v.x, v.y, hp, lp);
            split_store(v.z, v.w, hp + 2, lp + 2);
        }
    };

    const int warp = tid >> 5, lane = tid & 31;
    const int wm = warp & 3, wn = warp >> 2;
    const int g = lane >> 2, tc = lane & 3;

    float acc[2][8][4];
    #pragma unroll
    for (int i = 0; i < 2; i++)
        #pragma unroll
        for (int j = 0; j < 8; j++)
            #pragma unroll
            for (int e = 0; e < 4; e++) acc[i][j][e] = 0.f;

    load_stage(0, sm);
    __syncthreads();

    #pragma unroll
    for (int kt = 0; kt < 8; kt++) {
        if (kt < 7) load_stage((kt + 1) * 32, sm + ((kt + 1) & 1) * STG);

        const __nv_bfloat16* st = sm + (kt & 1) * STG;
        const __nv_bfloat16* Ah = st;
        const __nv_bfloat16* Al = st + 5120;
        const __nv_bfloat16* Bh = st + 10240;
        const __nv_bfloat16* Bl = st + 15360;

        #pragma unroll
        for (int kk = 0; kk < 2; kk++) {
            const int kc = kk * 16 + tc * 2;
            uint ah[2][4], al[2][4];
            #pragma unroll
            for (int mi = 0; mi < 2; mi++) {
                int row = wm * 32 + mi * 16 + g;
                ah[mi][0] = lds_u32(Ah + row * LDT + kc);
                ah[mi][1] = lds_u32(Ah + (row + 8) * LDT + kc);
                ah[mi][2] = lds_u32(Ah + row * LDT + kc + 8);
                ah[mi][3] = lds_u32(Ah + (row + 8) * LDT + kc + 8);
                al[mi][0] = lds_u32(Al + row * LDT + kc);
                al[mi][1] = lds_u32(Al + (row + 8) * LDT + kc);
                al[mi][2] = lds_u32(Al + row * LDT + kc + 8);
                al[mi][3] = lds_u32(Al + (row + 8) * LDT + kc + 8);
            }
            #pragma unroll
            for (int nj = 0; nj < 8; nj++) {
                int n = wn * 64 + nj * 8 + g;
                uint bh[2], bl[2];
                bh[0] = lds_u32(Bh + n * LDT + kc);
                bh[1] = lds_u32(Bh + n * LDT + kc + 8);
                bl[0] = lds_u32(Bl + n * LDT + kc);
                bl[1] = lds_u32(Bl + n * LDT + kc + 8);
                #pragma unroll
                for (int mi = 0; mi < 2; mi++) {
                    mma16816(acc[mi][nj], ah[mi], bh);
                    mma16816(acc[mi][nj], al[mi], bh);
                    mma16816(acc[mi][nj], ah[mi], bl);
                }
            }
        }
        __syncthreads();
    }

    #pragma unroll
    for (int mi = 0; mi < 2; mi++) {
        #pragma unroll
        for (int nj = 0; nj < 8; nj++) {
            int row = m0 + wm * 32 + mi * 16 + g;
            int col = n0 + wn * 64 + nj * 8 + tc * 2;
            float b0 = __ldg(bias + col), b1 = __ldg(bias + col + 1);
            float2 o0 = make_float2(acc[mi][nj][0] + b0, acc[mi][nj][1] + b1);
            float2 o1 = make_float2(acc[mi][nj][2] + b0, acc[mi][nj][3] + b1);
            *reinterpret_cast<float2*>(C + (size_t)row * N + col) = o0;
            *reinterpret_cast<float2*>(C + (size_t)(row + 8) * N + col) = o1;
        }
    }
}

// =============================================================================
// Fused attention: one CTA per (b, t). 512 threads = 16 warps = 2 warps/head.
// Each warp: 32 query rows x 64 keys for its head. bf16x3 MMA for q@k^T and
// P@v; fp32 softmax; relative-position bias gathered from smem table.
// =============================================================================
__global__ __launch_bounds__(512, 1) void attn_kernel(const float* __restrict__ rpb)
{
    extern __shared__ __nv_bfloat16 sm[];
    // layout (bf16 units):
    //   qhi 64x264, qlo, khi 64x264, klo       (4 x 16896)
    //   vhi_t 256x72, vlo_t 256x72 (v transposed: [d][seq])
    //   rpb table: 1800 floats
    __nv_bfloat16* qhi = sm;
    __nv_bfloat16* qlo = sm + 16896;
    __nv_bfloat16* khi = sm + 2 * 16896;
    __nv_bfloat16* klo = sm + 3 * 16896;
    __nv_bfloat16* vhi = sm + 4 * 16896;
    __nv_bfloat16* vlo = sm + 4 * 16896 + 18432;
    float* srpb = reinterpret_cast<float*>(sm + 4 * 16896 + 2 * 18432);

    const int tid = threadIdx.x;
    const int bt = blockIdx.x;          // b * 2 + t
    const int b = bt >> 1;

    const float* qsrc = g_q + (size_t)b * (64 * 256);
    const float* kvsrc = g_kv + (size_t)bt * (64 * 512);

    // ---- stage q (64x256) ----
    #pragma unroll
    for (int u = 0; u < 8; u++) {
        int f = tid + u * 512;
        int r = f >> 6;
        int c = (f & 63) << 2;
        float4 v = *reinterpret_cast<const float4*>(qsrc + r * 256 + c);
        split_store(v.x, v.y, qhi + r * 264 + c, qlo + r * 264 + c);
        split_store(v.z, v.w, qhi + r * 264 + c + 2, qlo + r * 264 + c + 2);
    }
    // ---- stage k (kv cols 0..255) ----
    #pragma unroll
    for (int u = 0; u < 8; u++) {
        int f = tid + u * 512;
        int r = f >> 6;
        int c = (f & 63) << 2;
        float4 v = *reinterpret_cast<const float4*>(kvsrc + r * 512 + c);
        split_store(v.x, v.y, khi + r * 264 + c, klo + r * 264 + c);
        split_store(v.z, v.w, khi + r * 264 + c + 2, klo + r * 264 + c + 2);
    }
    // ---- stage v transposed (kv cols 256..511 -> v_t[d][seq]) ----
    #pragma unroll
    for (int u = 0; u < 8; u++) {
        int f = tid + u * 512;
        int r = f >> 6;                 // seq
        int c = (f & 63) << 2;          // d base
        float4 v = *reinterpret_cast<const float4*>(kvsrc + r * 512 + 256 + c);
        float vals[4] = {v.x, v.y, v.z, v.w};
        #pragma unroll
        for (int j = 0; j < 4; j++) {
            __nv_bfloat16 hb = __float2bfloat16(vals[j]);
            vhi[(c + j) * 72 + r] = hb;
            vlo[(c + j) * 72 + r] = __float2bfloat16(vals[j] - __bfloat162float(hb));
        }
    }
    for (int i = tid; i < 1800; i += 512) srpb[i] = rpb[i];
    __syncthreads();

    const int warp = tid >> 5, lane = tid & 31;
    const int h = warp >> 1, half = warp & 1;
    const int g = lane >> 2, tc = lane & 3;
    const int r0 = half * 32;

    // ---- S = q @ k^T for this head/half (32 x 64) ----
    float S[2][8][4];
    #pragma unroll
    for (int i = 0; i < 2; i++)
        #pragma unroll
        for (int j = 0; j < 8; j++)
            #pragma unroll
            for (int e = 0; e < 4; e++) S[i][j][e] = 0.f;

    #pragma unroll
    for (int kk = 0; kk < 2; kk++) {
        const int kc = h * 32 + kk * 16 + tc * 2;
        uint ah[2][4], al[2][4];
        #pragma unroll
        for (int mi = 0; mi < 2; mi++) {
            int row = r0 + mi * 16 + g;
            ah[mi][0] = lds_u32(qhi + row * 264 + kc);
            ah[mi][1] = lds_u32(qhi + (row + 8) * 264 + kc);
            ah[mi][2] = lds_u32(qhi + row * 264 + kc + 8);
            ah[mi][3] = lds_u32(qhi + (row + 8) * 264 + kc + 8);
            al[mi][0] = lds_u32(qlo + row * 264 + kc);
            al[mi][1] = lds_u32(qlo + (row + 8) * 264 + kc);
            al[mi][2] = lds_u32(qlo + row * 264 + kc + 8);
            al[mi][3] = lds_u32(qlo + (row + 8) * 264 + kc + 8);
        }
        #pragma unroll
        for (int nj = 0; nj < 8; nj++) {
            int n = nj * 8 + g;
            uint bh[2], bl[2];
            bh[0] = lds_u32(khi + n * 264 + kc);
            bh[1] = lds_u32(khi + n * 264 + kc + 8);
            bl[0] = lds_u32(klo + n * 264 + kc);
            bl[1] = lds_u32(klo + n * 264 + kc + 8);
            #pragma unroll
            for (int mi = 0; mi < 2; mi++) {
                mma16816(S[mi][nj], ah[mi], bh);
                mma16816(S[mi][nj], al[mi], bh);
                mma16816(S[mi][nj], ah[mi], bl);
            }
        }
    }

    // ---- scale + relative-position bias + softmax (fp32) ----
    const float scale = 0.17677669529663687f;   // 32^-0.5
    #pragma unroll
    for (int mi = 0; mi < 2; mi++) {
        #pragma unroll
        for (int p = 0; p < 2; p++) {           // row g and row g+8
            int row = r0 + mi * 16 + g + p * 8;
            int pi = row >> 3, pj = row & 7;
            float mx = -1e30f;
            #pragma unroll
            for (int nj = 0; nj < 8; nj++) {
                #pragma unroll
                for (int e = 0; e < 2; e++) {
                    int col = nj * 8 + tc * 2 + e;
                    int qi = col >> 3, qj = col & 7;
                    int rel = (pi - qi + 7) * 15 + (pj - qj + 7);
                    float s = S[mi][nj][p * 2 + e] * scale + srpb[rel * 8 + h];
                    S[mi][nj][p * 2 + e] = s;
                    mx = fmaxf(mx, s);
                }
            }
            mx = fmaxf(mx, __shfl_xor_sync(0xffffffffu, mx, 1));
            mx = fmaxf(mx, __shfl_xor_sync(0xffffffffu, mx, 2));
            float sum = 0.f;
            #pragma unroll
            for (int nj = 0; nj < 8; nj++) {
                #pragma unroll
                for (int e = 0; e < 2; e++) {
                    float pe = __expf(S[mi][nj][p * 2 + e] - mx);
                    S[mi][nj][p * 2 + e] = pe;
                    sum += pe;
                }
            }
            sum += __shfl_xor_sync(0xffffffffu, sum, 1);
            sum += __shfl_xor_sync(0xffffffffu, sum, 2);
            float inv = 1.f / sum;
            #pragma unroll
            for (int nj = 0; nj < 8; nj++) {
                S[mi][nj][p * 2 + 0] *= inv;
                S[mi][nj][p * 2 + 1] *= inv;
            }
        }
    }

    // ---- O = P @ v  (pack P frags per k-tile to bound register pressure) ----
    float O[2][4][4];
    #pragma unroll
    for (int i = 0; i < 2; i++)
        #pragma unroll
        for (int j = 0; j < 4; j++)
            #pragma unroll
            for (int e = 0; e < 4; e++) O[i][j][e] = 0.f;

    #pragma unroll
    for (int t = 0; t < 4; t++) {               // k-tiles over 64 keys
        uint phi[2][4], plo[2][4];
        #pragma unroll
        for (int mi = 0; mi < 2; mi++) {
            packsplit(S[mi][2 * t][0], S[mi][2 * t][1], phi[mi][0], plo[mi][0]);
            packsplit(S[mi][2 * t][2], S[mi][2 * t][3], phi[mi][1], plo[mi][1]);
            packsplit(S[mi][2 * t + 1][0], S[mi][2 * t + 1][1], phi[mi][2], plo[mi][2]);
            packsplit(S[mi][2 * t + 1][2], S[mi][2 * t + 1][3], phi[mi][3], plo[mi][3]);
        }
        const int kb = t * 16 + tc * 2;
        #pragma unroll
        for (int jn = 0; jn < 4; jn++) {
            int d = h * 32 + jn * 8 + g;
            uint bh[2], bl[2];
            bh[0] = lds_u32(vhi + d * 72 + kb);
            bh[1] = lds_u32(vhi + d * 72 + kb + 8);
            bl[0] = lds_u32(vlo + d * 72 + kb);
            bl[1] = lds_u32(vlo + d * 72 + kb + 8);
            #pragma unroll
            for (int mi = 0; mi < 2; mi++) {
                mma16816(O[mi][jn], phi[mi], bh);
                mma16816(O[mi][jn], plo[mi], bh);
                mma16816(O[mi][jn], phi[mi], bl);
            }
        }
    }

    // ---- write O merged-head: g_att[(bt*64 + row)*256 + h*32 + d] ----
    float* dst = g_att + (size_t)bt * (64 * 256);
    #pragma unroll
    for (int mi = 0; mi < 2; mi++) {
        #pragma unroll
        for (int jn = 0; jn < 4; jn++) {
            int row = r0 + mi * 16 + g;
            int col = h * 32 + jn * 8 + tc * 2;
            *reinterpret_cast<float2*>(dst + row * 256 + col) =
                make_float2(O[mi][jn][0], O[mi][jn][1]);
            *reinterpret_cast<float2*>(dst + (row + 8) * 256 + col) =
                make_float2(O[mi][jn][2], O[mi][jn][3]);
        }
    }
}

// =============================================================================
extern "C" void kernel_launch(void* const* d_in, const int* in_sizes, int n_in,
                              void* d_out, int out_size)
{
    const float* x      = (const float*)d_in[0];
    const float* memory = (const float*)d_in[1];
    const float* q_w    = (const float*)d_in[2];
    const float* q_b    = (const float*)d_in[3];
    const float* kv_w   = (const float*)d_in[4];
    const float* kv_b   = (const float*)d_in[5];
    const float* proj_w = (const float*)d_in[6];
    const float* proj_b = (const float*)d_in[7];
    const float* rpb    = (const float*)d_in[8];
    float* out = (float*)d_out;

    float *qbuf = nullptr, *kvbuf = nullptr, *attbuf = nullptr;
    cudaGetSymbolAddress((void**)&qbuf, g_q);
    cudaGetSymbolAddress((void**)&kvbuf, g_kv);
    cudaGetSymbolAddress((void**)&attbuf, g_att);

    cudaFuncSetAttribute(gemm_bias_kernel,
                         cudaFuncAttributeMaxDynamicSharedMemorySize, 81920);
    cudaFuncSetAttribute(attn_kernel,
                         cudaFuncAttributeMaxDynamicSharedMemorySize, 216096);

    // q projection: (2048*64, 256) @ (256, 256)^T
    gemm_bias_kernel<<<dim3(2, 1024), 256, 81920>>>(x, q_w, q_b, qbuf, 256);
    // kv projection: (4096*64, 256) @ (512, 256)^T
    gemm_bias_kernel<<<dim3(4, 2048), 256, 81920>>>(memory, kv_w, kv_b, kvbuf, 512);
    // fused attention per (b, t)
    attn_kernel<<<4096, 512, 216096>>>(rpb);
    // output projection: (4096*64, 256) @ (256, 256)^T
    gemm_bias_kernel<<<dim3(2, 2048), 256, 81920>>>(attbuf, proj_w, proj_b, out, 256);
}